// round 4
// baseline (speedup 1.0000x reference)
#include <cuda_runtime.h>

__device__ double   g_acc[2];   // [0]=flow0 (kz=3), [1]=flow1 (kz=5)
__device__ unsigned g_cnt = 0;

// Warp-strip separable affine residual with analytic S2:
//   sum_windows p^T (I-P) p
//     = sum_pixels cr(i)*cc(j)*g^2  -  sum_windows [ (Sa^2+Sc^2)/D1 + S0^2/D0 ]
// (cr/cc = separable per-pixel window-coverage counts; coordinate grids are
// affine in patch offsets and annihilated by I-P, so flow values alone suffice.)
// Vertical kz-window sums V0/Va per column, incrementally updated; horizontal
// kz-window slides in registers; halo columns come from lane+1 via shfl.
template <int KZ, int W, int CPT, int CH, bool KEEP>
__device__ __forceinline__ void strip_residual(const float* __restrict__ plane,
                                               int i0, int lane, bool last,
                                               float& pA, float& pB, float& wg2) {
    constexpr int   HOUT = W - KZ + 1;
    constexpr int   HW   = CPT + KZ - 1;
    constexpr float m    = (KZ - 1) * 0.5f;

    const int col0   = lane * CPT;
    const int own_hi = last ? W : (i0 + CH);   // rows this task owns for wg2

    // Per-lane column coverage counts cc(j).
    float cc[CPT];
#pragma unroll
    for (int q = 0; q < CPT; ++q) {
        const int jg = col0 + q;
        const int v  = min(jg, KZ - 1) - max(0, jg - (HOUT - 1)) + 1;
        cc[q] = (float)max(v, 0);
    }

    const float* __restrict__ p = plane + (size_t)i0 * W + col0;

    float r[KZ][CPT];              // only materialized when KEEP
    float V0[CPT], Va[CPT];
#pragma unroll
    for (int c = 0; c < CPT; ++c) { V0[c] = 0.f; Va[c] = 0.f; }

    // Initial vertical sums + weighted g^2 for owned init rows.
#pragma unroll
    for (int a = 0; a < KZ; ++a) {
        const int  rg  = i0 + a;
        const float crf = (rg < own_hi)
            ? (float)(min(rg, KZ - 1) - max(0, rg - (HOUT - 1)) + 1) : 0.f;
        float rowacc = 0.f;
#pragma unroll
        for (int v = 0; v < CPT / 4; ++v) {
            float4 t = *reinterpret_cast<const float4*>(p + (size_t)a * W + v * 4);
            float g4[4] = {t.x, t.y, t.z, t.w};
#pragma unroll
            for (int q = 0; q < 4; ++q) {
                const int c = v * 4 + q;
                const float g = g4[q];
                V0[c] += g;
                Va[c] = fmaf((float)a - m, g, Va[c]);
                rowacc = fmaf(cc[c], g * g, rowacc);
                if (KEEP) r[a][c] = g;
            }
        }
        wg2 = fmaf(crf, rowacc, wg2);
    }

#pragma unroll
    for (int ii = 0; ii < CH; ++ii) {
        // Halo vertical sums from lane+1 (lane 31's halo feeds only
        // predicated-off outputs).
        float h0[HW], ha[HW];
#pragma unroll
        for (int c = 0; c < CPT; ++c) { h0[c] = V0[c]; ha[c] = Va[c]; }
#pragma unroll
        for (int k = 0; k < KZ - 1; ++k) {
            h0[CPT + k] = __shfl_down_sync(0xffffffffu, V0[k], 1);
            ha[CPT + k] = __shfl_down_sync(0xffffffffu, Va[k], 1);
        }

        float S0 = 0.f, Sa = 0.f, Sc = 0.f;
#pragma unroll
        for (int c = 0; c < KZ; ++c) {
            S0 += h0[c];
            Sc = fmaf((float)c - m, h0[c], Sc);
            Sa += ha[c];
        }
#pragma unroll
        for (int j = 0; j < CPT; ++j) {
            if (col0 + j < HOUT) {
                float t = Sa * Sa;
                t  = fmaf(Sc, Sc, t);
                pA += t;
                pB = fmaf(S0, S0, pB);
            }
            if (j + 1 < CPT) {
                const float d0 = h0[j], dn = h0[j + KZ];
                Sc = Sc - S0;
                Sc = fmaf(m + 1.f, d0, Sc);
                Sc = fmaf(m, dn, Sc);
                S0 += dn - d0;
                Sa += ha[j + KZ] - ha[j];
            }
        }

        // Vertical slide: drop row ii, add row ii+KZ (+ its weighted g^2).
        if (ii + 1 < CH) {
            const float* pn = p + (size_t)(ii + KZ) * W;
            const float* po = p + (size_t)ii * W;          // L1-resident reload
            const int   rg  = i0 + ii + KZ;
            const float crf = (rg < own_hi)
                ? (float)(min(rg, KZ - 1) - max(0, rg - (HOUT - 1)) + 1) : 0.f;
            float rowacc = 0.f;
#pragma unroll
            for (int v = 0; v < CPT / 4; ++v) {
                float4 tn = *reinterpret_cast<const float4*>(pn + v * 4);
                float gn4[4] = {tn.x, tn.y, tn.z, tn.w};
                float gd4[4];
                if (KEEP) {
#pragma unroll
                    for (int q = 0; q < 4; ++q) gd4[q] = r[(ii) % KZ][v * 4 + q];
                } else {
                    float4 to = *reinterpret_cast<const float4*>(po + v * 4);
                    gd4[0] = to.x; gd4[1] = to.y; gd4[2] = to.z; gd4[3] = to.w;
                }
#pragma unroll
                for (int q = 0; q < 4; ++q) {
                    const int c = v * 4 + q;
                    const float gd = gd4[q], gn = gn4[q];
                    float t = Va[c] - V0[c];
                    t = fmaf(m + 1.f, gd, t);
                    Va[c] = fmaf(m, gn, t);
                    V0[c] += gn - gd;
                    rowacc = fmaf(cc[c], gn * gn, rowacc);
                    if (KEEP) r[(ii) % KZ][c] = gn;
                }
            }
            wg2 = fmaf(crf, rowacc, wg2);
        }
    }
}

// 672 blocks x 8 warps. Warps 0..5: heavy (kz=5, flow1), 64 planes x 63
// chunks of 4 rows = 4032 tasks. Warps 6..7: light (kz=3, flow0), 64 planes
// x 21 chunks of 6 rows = 1344 tasks. Every block has an identical 6H+2L mix.
__global__ __launch_bounds__(256, 4)
void fused_loss_kernel(const float* __restrict__ f0,
                       const float* __restrict__ f1,
                       float* __restrict__ out) {
    const int wid  = threadIdx.x >> 5;
    const int lane = threadIdx.x & 31;

    float pA = 0.f, pB = 0.f, wg2 = 0.f;
    float partial;
    int   which;

    if (wid < 6) {                              // heavy: kz=5 on flow1
        const int idx   = blockIdx.x * 6 + wid; // 0..4031
        const int plane = idx / 63, chunk = idx % 63;
        strip_residual<5, 256, 8, 4, false>(f1 + (size_t)plane * 256 * 256,
                                            chunk * 4, lane, chunk == 62,
                                            pA, pB, wg2);
        constexpr float invD1 = 12.0f / (25.0f * 24.0f);
        constexpr float invD0 = 1.0f / 25.0f;
        partial = wg2 - pA * invD1 - pB * invD0;
        which = 1;
    } else {                                    // light: kz=3 on flow0
        const int idx   = blockIdx.x * 2 + (wid - 6);   // 0..1343
        const int plane = idx / 21, chunk = idx % 21;
        strip_residual<3, 128, 4, 6, true>(f0 + (size_t)plane * 128 * 128,
                                           chunk * 6, lane, chunk == 20,
                                           pA, pB, wg2);
        constexpr float invD1 = 12.0f / (9.0f * 8.0f);
        constexpr float invD0 = 1.0f / 9.0f;
        partial = wg2 - pA * invD1 - pB * invD0;
        which = 0;
    }

#pragma unroll
    for (int off = 16; off > 0; off >>= 1)
        partial += __shfl_down_sync(0xffffffffu, partial, off);

    __shared__ double sh[8];
    if (lane == 0) sh[wid] = (double)partial;
    __syncthreads();

    if (threadIdx.x == 0) {
        double a1 = 0.0, a0 = 0.0;
#pragma unroll
        for (int w = 0; w < 6; ++w) a1 += sh[w];
        a0 = sh[6] + sh[7];
        atomicAdd(&g_acc[0], a0);
        atomicAdd(&g_acc[1], a1);
        __threadfence();
        const unsigned done = atomicAdd(&g_cnt, 1);
        if (done == gridDim.x - 1) {            // last block: finalize + reset
            __threadfence();
            const double r0 = g_acc[0], r1 = g_acc[1];
            out[0] = (float)(r0 / (32.0 * 126.0 * 126.0) +
                             r1 / (32.0 * 252.0 * 252.0));
            g_acc[0] = 0.0; g_acc[1] = 0.0; g_cnt = 0u;
        }
    }
}

extern "C" void kernel_launch(void* const* d_in, const int* in_sizes, int n_in,
                              void* d_out, int out_size) {
    const float* flow0 = (const float*)d_in[0];  // (32, 2, 128, 128)
    const float* flow1 = (const float*)d_in[1];  // (32, 2, 256, 256)
    if (n_in >= 2 && in_sizes[0] > in_sizes[1]) {
        const float* t = flow0; flow0 = flow1; flow1 = t;
    }
    fused_loss_kernel<<<672, 256>>>(flow0, flow1, (float*)d_out);
}

// round 5
// speedup vs baseline: 1.6157x; 1.6157x over previous
#include <cuda_runtime.h>

__device__ double   g_acc[2];   // [0]=flow0 (kz=3), [1]=flow1 (kz=5)
__device__ unsigned g_cnt = 0;

// Warp-strip separable affine residual, analytic S2, shfl-free:
//   sum_windows p^T (I-P) p
//     = sum_pixels cr(i)*cc(j)*g^2 - sum_windows [ (Sa^2+Sc^2)/D1 + S0^2/D0 ]
// Each lane loads OVERLAPPING columns (own CPT + KZ-1 halo) so the horizontal
// windows need no cross-lane exchange. Vertical kz-window sums V0/Va per
// column, incrementally updated (dropped row reloaded from L1).
template <int KZ, int W, int CPT, int NLD>
__device__ __forceinline__ void strip_residual(const float* __restrict__ plane,
                                               int i0, int rows, int own_hi,
                                               int lane,
                                               float& pA, float& pB, float& wg2) {
    constexpr int   HOUT = W - KZ + 1;
    constexpr int   NC   = NLD * 4;        // columns loaded per lane
    constexpr int   VU   = CPT + KZ - 1;   // columns needing vertical sums
    constexpr float m    = (KZ - 1) * 0.5f;

    const int  col0     = lane * CPT;
    const bool lastlane = (col0 + NC > W); // lane 31: last float4 would be OOB

    // Column coverage counts cc(j) for OWN columns only.
    float cc[CPT];
#pragma unroll
    for (int q = 0; q < CPT; ++q) {
        const int jg = col0 + q;
        const int v  = min(jg, KZ - 1) - max(0, jg - (HOUT - 1)) + 1;
        cc[q] = (float)max(v, 0);
    }

    const float* __restrict__ p = plane + (size_t)i0 * W + col0;

    float V0[VU], Va[VU];
#pragma unroll
    for (int c = 0; c < VU; ++c) { V0[c] = 0.f; Va[c] = 0.f; }

    // ---- init: rows i0 .. i0+KZ-1 ----
#pragma unroll
    for (int a = 0; a < KZ; ++a) {
        float g[NC];
#pragma unroll
        for (int v = 0; v < NLD; ++v) {
            if (v < NLD - 1 || !lastlane) {
                float4 t = *reinterpret_cast<const float4*>(p + (size_t)a * W + v * 4);
                g[v*4+0] = t.x; g[v*4+1] = t.y; g[v*4+2] = t.z; g[v*4+3] = t.w;
            } else {
                g[v*4+0] = 0.f; g[v*4+1] = 0.f; g[v*4+2] = 0.f; g[v*4+3] = 0.f;
            }
        }
        const int rg = i0 + a;
        const float crf = (rg < own_hi)
            ? (float)max(min(rg, KZ - 1) - max(0, rg - (HOUT - 1)) + 1, 0) : 0.f;
        float rowacc = 0.f;
#pragma unroll
        for (int q = 0; q < VU; ++q) {
            V0[q] += g[q];
            Va[q] = fmaf((float)a - m, g[q], Va[q]);
        }
#pragma unroll
        for (int q = 0; q < CPT; ++q)
            rowacc = fmaf(cc[q], g[q] * g[q], rowacc);
        wg2 = fmaf(crf, rowacc, wg2);
    }

    // ---- main loop over output rows ----
    for (int ii = 0; ii < rows; ++ii) {
        // Horizontal windows from local V0/Va (no shfl).
        float S0 = 0.f, Sa = 0.f, Sc = 0.f;
#pragma unroll
        for (int c = 0; c < KZ; ++c) {
            S0 += V0[c];
            Sc = fmaf((float)c - m, V0[c], Sc);
            Sa += Va[c];
        }
#pragma unroll
        for (int j = 0; j < CPT; ++j) {
            if (col0 + j < HOUT) {
                pA = fmaf(Sa, Sa, pA);
                pA = fmaf(Sc, Sc, pA);
                pB = fmaf(S0, S0, pB);
            }
            if (j + 1 < CPT) {
                const float d0 = V0[j], dn = V0[j + KZ];
                Sc = Sc - S0;
                Sc = fmaf(m + 1.f, d0, Sc);
                Sc = fmaf(m, dn, Sc);
                S0 += dn - d0;
                Sa += Va[j + KZ] - Va[j];
            }
        }

        // Vertical slide: drop row i0+ii (L1 reload), add row i0+ii+KZ.
        if (ii + 1 < rows) {
            const float* pn = p + (size_t)(ii + KZ) * W;
            const float* po = p + (size_t)ii * W;
            const int rg = i0 + ii + KZ;
            const float crf = (rg < own_hi)
                ? (float)max(min(rg, KZ - 1) - max(0, rg - (HOUT - 1)) + 1, 0) : 0.f;
            float gn[NC], gd[NC];
#pragma unroll
            for (int v = 0; v < NLD; ++v) {
                if (v < NLD - 1 || !lastlane) {
                    float4 tn = *reinterpret_cast<const float4*>(pn + v * 4);
                    float4 to = *reinterpret_cast<const float4*>(po + v * 4);
                    gn[v*4+0]=tn.x; gn[v*4+1]=tn.y; gn[v*4+2]=tn.z; gn[v*4+3]=tn.w;
                    gd[v*4+0]=to.x; gd[v*4+1]=to.y; gd[v*4+2]=to.z; gd[v*4+3]=to.w;
                } else {
#pragma unroll
                    for (int q = 0; q < 4; ++q) { gn[v*4+q] = 0.f; gd[v*4+q] = 0.f; }
                }
            }
            float rowacc = 0.f;
#pragma unroll
            for (int q = 0; q < VU; ++q) {
                float t = Va[q] - V0[q];
                t = fmaf(m + 1.f, gd[q], t);
                Va[q] = fmaf(m, gn[q], t);
                V0[q] += gn[q] - gd[q];
            }
#pragma unroll
            for (int q = 0; q < CPT; ++q)
                rowacc = fmaf(cc[q], gn[q] * gn[q], rowacc);
            wg2 = fmaf(crf, rowacc, wg2);
        }
    }
}

// 444 blocks x 8 warps = 3552 warp-tasks; exactly 3 blocks per SM (444=3*148),
// every block an identical 6-heavy + 2-light mix -> perfectly balanced wave.
//   heavy (kz=5, flow1): 2664 tasks. Planes 0..39: 42 chunks of 6 rows.
//     Planes 40..63: 41 chunks (6 of 7 rows, then 35 of 6).  40*42+24*41=2664.
//   light (kz=3, flow0): 888 tasks. Planes 0..55: 14 chunks of 9 rows.
//     Planes 56..63: 13 chunks (9 of 10 rows, then 4 of 9).  56*14+8*13=888.
__global__ __launch_bounds__(256, 3)
void fused_loss_kernel(const float* __restrict__ f0,
                       const float* __restrict__ f1,
                       float* __restrict__ out) {
    const int wid  = threadIdx.x >> 5;
    const int lane = threadIdx.x & 31;

    float pA = 0.f, pB = 0.f, wg2 = 0.f;
    float partial;

    if (wid < 6) {                               // heavy: kz=5 on flow1
        const int h = blockIdx.x * 6 + wid;      // 0..2663
        int plane, i0, rows; bool last;
        if (h < 1680) {
            plane = h / 42; const int c = h % 42;
            i0 = c * 6; rows = 6; last = (c == 41);
        } else {
            const int k = h - 1680;
            plane = 40 + k / 41; const int c = k % 41;
            if (c < 6) { i0 = c * 7; rows = 7; }
            else       { i0 = 42 + (c - 6) * 6; rows = 6; }
            last = (c == 40);
        }
        const int own_hi = last ? 256 : (i0 + rows);
        strip_residual<5, 256, 8, 3>(f1 + (size_t)plane * 256 * 256,
                                     i0, rows, own_hi, lane, pA, pB, wg2);
        constexpr float invD1 = 12.0f / (25.0f * 24.0f);
        constexpr float invD0 = 1.0f / 25.0f;
        partial = wg2 - pA * invD1 - pB * invD0;
    } else {                                     // light: kz=3 on flow0
        const int l = blockIdx.x * 2 + (wid - 6); // 0..887
        int plane, i0, rows; bool last;
        if (l < 784) {
            plane = l / 14; const int c = l % 14;
            i0 = c * 9; rows = 9; last = (c == 13);
        } else {
            const int k = l - 784;
            plane = 56 + k / 13; const int c = k % 13;
            if (c < 9) { i0 = c * 10; rows = 10; }
            else       { i0 = 90 + (c - 9) * 9; rows = 9; }
            last = (c == 12);
        }
        const int own_hi = last ? 128 : (i0 + rows);
        strip_residual<3, 128, 4, 2>(f0 + (size_t)plane * 128 * 128,
                                     i0, rows, own_hi, lane, pA, pB, wg2);
        constexpr float invD1 = 12.0f / (9.0f * 8.0f);
        constexpr float invD0 = 1.0f / 9.0f;
        partial = wg2 - pA * invD1 - pB * invD0;
    }

#pragma unroll
    for (int off = 16; off > 0; off >>= 1)
        partial += __shfl_down_sync(0xffffffffu, partial, off);

    __shared__ double sh[8];
    if (lane == 0) sh[wid] = (double)partial;
    __syncthreads();

    if (threadIdx.x == 0) {
        double a1 = sh[0] + sh[1] + sh[2] + sh[3] + sh[4] + sh[5];
        double a0 = sh[6] + sh[7];
        atomicAdd(&g_acc[0], a0);
        atomicAdd(&g_acc[1], a1);
        __threadfence();
        const unsigned done = atomicAdd(&g_cnt, 1);
        if (done == gridDim.x - 1) {             // last block: finalize + reset
            __threadfence();
            const double r0 = g_acc[0], r1 = g_acc[1];
            out[0] = (float)(r0 / (32.0 * 126.0 * 126.0) +
                             r1 / (32.0 * 252.0 * 252.0));
            g_acc[0] = 0.0; g_acc[1] = 0.0; g_cnt = 0u;
        }
    }
}

extern "C" void kernel_launch(void* const* d_in, const int* in_sizes, int n_in,
                              void* d_out, int out_size) {
    const float* flow0 = (const float*)d_in[0];  // (32, 2, 128, 128)
    const float* flow1 = (const float*)d_in[1];  // (32, 2, 256, 256)
    if (n_in >= 2 && in_sizes[0] > in_sizes[1]) {
        const float* t = flow0; flow0 = flow1; flow1 = t;
    }
    fused_loss_kernel<<<444, 256>>>(flow0, flow1, (float*)d_out);
}

// round 7
// speedup vs baseline: 1.7657x; 1.0928x over previous
#include <cuda_runtime.h>

__device__ double   g_acc[2];   // [0]=flow0 (kz=3), [1]=flow1 (kz=5)
__device__ unsigned g_cnt = 0;

// Warp-strip separable affine residual, analytic S2, branch-free hot loop:
//   sum_windows p^T (I-P) p
//     = sum_pixels cr(i)*cc(j)*g^2 - sum_windows [ (Sa^2+Sc^2)/D1 + S0^2/D0 ]
// Each lane loads NC contiguous columns at col0 = min(lane*CPT, W-NC) — always
// in-bounds, no divergent guards. Duplicate windows/pixels from the shifted
// last lane are masked by loop-invariant predicates and zeroed cc weights.
// Vertical kz-window sums V0/Va per loaded column, incrementally updated
// (dropped row reloaded from L1). Slide loads issued BEFORE the horizontal
// sweep so L1 latency hides under ~100 cycles of independent fma work.
template <int KZ, int W, int CPT, int NLD>
__device__ __forceinline__ void strip_residual(const float* __restrict__ plane,
                                               int i0, int rows, int own_hi,
                                               int lane,
                                               float& pA, float& pB, float& wg2) {
    constexpr int   HOUT = W - KZ + 1;
    constexpr int   NC   = NLD * 4;          // columns loaded per lane
    constexpr int   JMAX = NC - KZ + 1;      // computable windows per lane
    constexpr float m    = (KZ - 1) * 0.5f;

    const int col0   = min(lane * CPT, W - NC);   // shifted base: always in-bounds
    const int own_lo = lane * CPT;                // first owned column
    const int own_hc = min(own_lo + CPT, HOUT);   // end of owned output cols

    // Per-loaded-column coverage weights (zero outside ownership).
    float ccq[NC];
#pragma unroll
    for (int q = 0; q < NC; ++q) {
        const int jg = col0 + q;
        const bool own = (jg >= own_lo) && (jg < own_lo + CPT);
        const int v = min(jg, KZ - 1) - max(0, jg - (HOUT - 1)) + 1;
        ccq[q] = own ? (float)max(v, 0) : 0.f;
    }

    const float* __restrict__ p = plane + (size_t)i0 * W + col0;

    float V0[NC], Va[NC];
#pragma unroll
    for (int c = 0; c < NC; ++c) { V0[c] = 0.f; Va[c] = 0.f; }

    // ---- init: rows i0 .. i0+KZ-1 (unguarded vector loads) ----
#pragma unroll
    for (int a = 0; a < KZ; ++a) {
        float g[NC];
#pragma unroll
        for (int v = 0; v < NLD; ++v) {
            float4 t = *reinterpret_cast<const float4*>(p + (size_t)a * W + v * 4);
            g[v*4+0] = t.x; g[v*4+1] = t.y; g[v*4+2] = t.z; g[v*4+3] = t.w;
        }
        const int rg = i0 + a;
        const float crf = (rg < own_hi)
            ? (float)max(min(rg, KZ - 1) - max(0, rg - (HOUT - 1)) + 1, 0) : 0.f;
        float rowacc = 0.f;
#pragma unroll
        for (int q = 0; q < NC; ++q) {
            V0[q] += g[q];
            Va[q] = fmaf((float)a - m, g[q], Va[q]);
            rowacc = fmaf(ccq[q], g[q] * g[q], rowacc);
        }
        wg2 = fmaf(crf, rowacc, wg2);
    }

    // ---- main loop over output rows ----
    for (int ii = 0; ii < rows; ++ii) {
        const bool doSlide = (ii + 1 < rows);

        // Issue next-slide loads FIRST (consumed after the sweep below).
        float gn[NC], gd[NC];
        if (doSlide) {
            const float* pn = p + (size_t)(ii + KZ) * W;
            const float* po = p + (size_t)ii * W;
#pragma unroll
            for (int v = 0; v < NLD; ++v) {
                float4 tn = *reinterpret_cast<const float4*>(pn + v * 4);
                float4 to = *reinterpret_cast<const float4*>(po + v * 4);
                gn[v*4+0]=tn.x; gn[v*4+1]=tn.y; gn[v*4+2]=tn.z; gn[v*4+3]=tn.w;
                gd[v*4+0]=to.x; gd[v*4+1]=to.y; gd[v*4+2]=to.z; gd[v*4+3]=to.w;
            }
        }

        // Horizontal sliding windows (independent of the loads above).
        float S0 = 0.f, Sa = 0.f, Sc = 0.f;
#pragma unroll
        for (int c = 0; c < KZ; ++c) {
            S0 += V0[c];
            Sc = fmaf((float)c - m, V0[c], Sc);
            Sa += Va[c];
        }
#pragma unroll
        for (int j = 0; j < JMAX; ++j) {
            const int jg = col0 + j;                    // loop-invariant preds
            if (jg >= own_lo && jg < own_hc) {
                pA = fmaf(Sa, Sa, pA);
                pA = fmaf(Sc, Sc, pA);
                pB = fmaf(S0, S0, pB);
            }
            if (j + 1 < JMAX) {
                const float d0 = V0[j], dn = V0[j + KZ];
                Sc = Sc - S0;
                Sc = fmaf(m + 1.f, d0, Sc);
                Sc = fmaf(m, dn, Sc);
                S0 += dn - d0;
                Sa += Va[j + KZ] - Va[j];
            }
        }

        // Vertical slide using the preloaded rows.
        if (doSlide) {
            const int rg = i0 + ii + KZ;
            const float crf = (rg < own_hi)
                ? (float)max(min(rg, KZ - 1) - max(0, rg - (HOUT - 1)) + 1, 0) : 0.f;
            float rowacc = 0.f;
#pragma unroll
            for (int q = 0; q < NC; ++q) {
                float t = Va[q] - V0[q];
                t = fmaf(m + 1.f, gd[q], t);
                Va[q] = fmaf(m, gn[q], t);
                V0[q] += gn[q] - gd[q];
                rowacc = fmaf(ccq[q], gn[q] * gn[q], rowacc);
            }
            wg2 = fmaf(crf, rowacc, wg2);
        }
    }
}

// 296 blocks x 8 warps = 2368 warp-tasks; exactly 2 blocks per SM (296=2*148),
// every block an identical 6-heavy + 2-light mix.
//   heavy (kz=5, flow1): 1776 tasks. Planes 0..47: 28 chunks of 9 rows.
//     Planes 48..63: 27 chunks (9 of 10 rows, 18 of 9). 48*28+16*27=1776.
//   light (kz=3, flow0):  592 tasks. Planes 0..47: 9 chunks of 14 rows.
//     Planes 48..63: 10 chunks (6 of 13, 4 of 12).     48*9+16*10=592.
__global__ __launch_bounds__(256, 2)
void fused_loss_kernel(const float* __restrict__ f0,
                       const float* __restrict__ f1,
                       float* __restrict__ out) {
    const int wid  = threadIdx.x >> 5;
    const int lane = threadIdx.x & 31;

    float pA = 0.f, pB = 0.f, wg2 = 0.f;
    float partial;

    if (wid < 6) {                                // heavy: kz=5 on flow1
        const int h = blockIdx.x * 6 + wid;       // 0..1775
        int plane, i0, rows; bool last;
        if (h < 1344) {
            plane = h / 28; const int c = h % 28;
            i0 = c * 9; rows = 9; last = (c == 27);
        } else {
            const int k = h - 1344;
            plane = 48 + k / 27; const int c = k % 27;
            if (c < 9) { i0 = c * 10; rows = 10; }
            else       { i0 = 90 + (c - 9) * 9; rows = 9; }
            last = (c == 26);
        }
        const int own_hi = last ? 256 : (i0 + rows);
        strip_residual<5, 256, 8, 3>(f1 + (size_t)plane * 256 * 256,
                                     i0, rows, own_hi, lane, pA, pB, wg2);
        constexpr float invD1 = 12.0f / (25.0f * 24.0f);
        constexpr float invD0 = 1.0f / 25.0f;
        partial = wg2 - pA * invD1 - pB * invD0;
    } else {                                      // light: kz=3 on flow0
        const int l = blockIdx.x * 2 + (wid - 6); // 0..591
        int plane, i0, rows; bool last;
        if (l < 432) {
            plane = l / 9; const int c = l % 9;
            i0 = c * 14; rows = 14; last = (c == 8);
        } else {
            const int k = l - 432;
            plane = 48 + k / 10; const int c = k % 10;
            if (c < 6) { i0 = c * 13; rows = 13; }
            else       { i0 = 78 + (c - 6) * 12; rows = 12; }
            last = (c == 9);
        }
        const int own_hi = last ? 128 : (i0 + rows);
        strip_residual<3, 128, 4, 2>(f0 + (size_t)plane * 128 * 128,
                                     i0, rows, own_hi, lane, pA, pB, wg2);
        constexpr float invD1 = 12.0f / (9.0f * 8.0f);
        constexpr float invD0 = 1.0f / 9.0f;
        partial = wg2 - pA * invD1 - pB * invD0;
    }

#pragma unroll
    for (int off = 16; off > 0; off >>= 1)
        partial += __shfl_down_sync(0xffffffffu, partial, off);

    __shared__ double sh[8];
    if (lane == 0) sh[wid] = (double)partial;
    __syncthreads();

    if (threadIdx.x == 0) {
        double a1 = sh[0] + sh[1] + sh[2] + sh[3] + sh[4] + sh[5];
        double a0 = sh[6] + sh[7];
        atomicAdd(&g_acc[0], a0);
        atomicAdd(&g_acc[1], a1);
        __threadfence();
        const unsigned done = atomicAdd(&g_cnt, 1);
        if (done == gridDim.x - 1) {              // last block: finalize + reset
            __threadfence();
            const double r0 = g_acc[0], r1 = g_acc[1];
            out[0] = (float)(r0 / (32.0 * 126.0 * 126.0) +
                             r1 / (32.0 * 252.0 * 252.0));
            g_acc[0] = 0.0; g_acc[1] = 0.0; g_cnt = 0u;
        }
    }
}

extern "C" void kernel_launch(void* const* d_in, const int* in_sizes, int n_in,
                              void* d_out, int out_size) {
    const float* flow0 = (const float*)d_in[0];  // (32, 2, 128, 128)
    const float* flow1 = (const float*)d_in[1];  // (32, 2, 256, 256)
    if (n_in >= 2 && in_sizes[0] > in_sizes[1]) {
        const float* t = flow0; flow0 = flow1; flow1 = t;
    }
    fused_loss_kernel<<<296, 256>>>(flow0, flow1, (float*)d_out);
}